// round 16
// baseline (speedup 1.0000x reference)
#include <cuda_runtime.h>
#include <cuda_fp16.h>
#include <math.h>
#include <stdint.h>

// ---------------------------------------------------------------------------
// Problem constants
// ---------------------------------------------------------------------------
#define B_   8
#define S_   1024
#define D_   768
#define F_   3072
#define H_   12
#define DK_  64
#define M_   (B_ * S_)       // 8192 rows

// ---------------------------------------------------------------------------
// Scratch (device globals; no allocation allowed)
// ---------------------------------------------------------------------------
__device__ __align__(16) __half g_xh [M_ * D_];              // x fp16
__device__ __align__(16) __half g_qh [B_ * H_ * S_ * DK_];   // [B,H,S,dk]
__device__ __align__(16) __half g_kh [B_ * H_ * S_ * DK_];   // [B,H,S,dk]
__device__ __align__(16) __half g_vth[B_ * H_ * DK_ * S_];   // [B,H,dk,S]
__device__ __align__(16) __half g_att[M_ * D_];              // attn out fp16
__device__ __align__(16) __half g_ffh[M_ * F_];              // gelu out fp16
__device__ __align__(16) __half g_o1h[M_ * D_];              // LN1 out fp16
__device__ __align__(16) __half g_tmph[M_ * D_];             // residual branch fp16
__device__ __align__(16) float g_out1[M_ * D_];              // LN1 out fp32
// transposed weights, [N, K] K-major, fp16. QKV concatenated.
__device__ __align__(16) __half g_wqkvT[3 * D_ * D_];
__device__ __align__(16) __half g_woT[D_ * D_];
__device__ __align__(16) __half g_w1T[F_ * D_];
__device__ __align__(16) __half g_w2T[D_ * F_];

// ---------------------------------------------------------------------------
// Helpers
// ---------------------------------------------------------------------------
__device__ __forceinline__ uint32_t smem_u32(const void* p) {
    uint32_t a;
    asm("{ .reg .u64 t; cvta.to.shared.u64 t, %1; cvt.u32.u64 %0, t; }"
        : "=r"(a) : "l"(p));
    return a;
}

__device__ __forceinline__ void cp16(uint32_t dst, const void* src) {
    asm volatile("cp.async.cg.shared.global [%0], [%1], 16;"
                 :: "r"(dst), "l"(src) : "memory");
}
__device__ __forceinline__ void cp4(uint32_t dst, const void* src) {
    asm volatile("cp.async.ca.shared.global [%0], [%1], 4;"
                 :: "r"(dst), "l"(src) : "memory");
}
#define CP_COMMIT asm volatile("cp.async.commit_group;" ::: "memory")
#define CP_WAIT1  asm volatile("cp.async.wait_group 1;" ::: "memory")

// m16n8k16 FP16 MMA (fp32 accumulate)
__device__ __forceinline__ void mma16(float* c,
                                      uint32_t a0, uint32_t a1, uint32_t a2, uint32_t a3,
                                      uint32_t b0, uint32_t b1)
{
    asm volatile(
        "mma.sync.aligned.m16n8k16.row.col.f32.f16.f16.f32 "
        "{%0,%1,%2,%3}, {%4,%5,%6,%7}, {%8,%9}, {%0,%1,%2,%3};"
        : "+f"(c[0]), "+f"(c[1]), "+f"(c[2]), "+f"(c[3])
        : "r"(a0), "r"(a1), "r"(a2), "r"(a3), "r"(b0), "r"(b1));
}

// ldmatrix x4 (b16, non-transposed)
__device__ __forceinline__ void ldsm4(uint32_t& r0, uint32_t& r1,
                                      uint32_t& r2, uint32_t& r3, uint32_t addr)
{
    asm volatile("ldmatrix.sync.aligned.m8n8.x4.shared.b16 {%0,%1,%2,%3}, [%4];"
                 : "=r"(r0), "=r"(r1), "=r"(r2), "=r"(r3) : "r"(addr));
}

// pack two fp32 -> f16x2 (lo = first arg)
__device__ __forceinline__ uint32_t pack_f16(float lo, float hi) {
    uint32_t r;
    asm("cvt.rn.f16x2.f32 %0, %1, %2;" : "=r"(r) : "f"(hi), "f"(lo));
    return r;
}

__device__ __forceinline__ float gelu_t(float x) {
    const float c = 0.7978845608028654f;
    float t = tanhf(c * (x + 0.044715f * x * x * x));
    return 0.5f * x * (1.0f + t);
}

// ---------------------------------------------------------------------------
// Fused prep kernel: all 6 weight transposes (fp16) + x -> fp16 conversion.
// ---------------------------------------------------------------------------
__device__ __forceinline__ void transpose_tile_f16(
    const float* __restrict__ W, __half* __restrict__ Wt,
    int K, int N, int k0, int n0, int tx, int ty)
{
    __shared__ float t[32][33];
#pragma unroll
    for (int i = 0; i < 32; i += 8)
        t[ty + i][tx] = W[(size_t)(k0 + ty + i) * N + n0 + tx];
    __syncthreads();
#pragma unroll
    for (int i = 0; i < 32; i += 8)
        Wt[(size_t)(n0 + ty + i) * K + k0 + tx] = __float2half_rn(t[tx][ty + i]);
}

__global__ void __launch_bounds__(256)
prep_kernel(const float* __restrict__ x,
            const float* __restrict__ Wq, const float* __restrict__ Wk,
            const float* __restrict__ Wv, const float* __restrict__ Wo,
            const float* __restrict__ W1, const float* __restrict__ W2,
            uint2* __restrict__ xh, __half* __restrict__ wqkvT,
            __half* __restrict__ woT, __half* __restrict__ w1T,
            __half* __restrict__ w2T)
{
    const int bx  = blockIdx.x;
    const int tid = threadIdx.x;
    const int tx  = tid & 31;
    const int ty  = tid >> 5;

    if (bx < 2304) {
        const int z = bx / 576, t = bx % 576;
        const int kx = t % 24, ny = t / 24;
        const float* W = (z == 0) ? Wq : (z == 1) ? Wk : (z == 2) ? Wv : Wo;
        __half* Wt = (z < 3) ? (wqkvT + (size_t)z * D_ * D_) : woT;
        transpose_tile_f16(W, Wt, D_, D_, kx * 32, ny * 32, tx, ty);
    } else if (bx < 4608) {
        const int t = bx - 2304;
        const int kx = t % 24, ny = t / 24;
        transpose_tile_f16(W1, w1T, D_, F_, kx * 32, ny * 32, tx, ty);
    } else if (bx < 6912) {
        const int t = bx - 4608;
        const int kx = t % 96, ny = t / 96;
        transpose_tile_f16(W2, w2T, F_, D_, kx * 32, ny * 32, tx, ty);
    } else {
        const int i = (bx - 6912) * 256 + tid;
        float4 v = ((const float4*)x)[i];
        uint2 o;
        o.x = pack_f16(v.x, v.y);
        o.y = pack_f16(v.z, v.w);
        xh[i] = o;
    }
}

// ---------------------------------------------------------------------------
// Shared epilogue (fp32 accumulators -> various output formats)
//   EPI: 3 fp16 head-split [B,H,S,dk], 4 fp16 transposed head-split [B,H,dk,S],
//        5 gelu -> fp16 row-major, 6 plain fp16 row-major
// ---------------------------------------------------------------------------
template <int EPI>
__device__ __forceinline__ void epilogue(
    float acc[4][8][4], const float* __restrict__ bias, void* __restrict__ C,
    int N, int m0, int n0, int wm, int wn, int lq, int tq)
{
#pragma unroll
    for (int mi = 0; mi < 4; mi++) {
        const int r0 = m0 + wm + mi * 16 + lq;
#pragma unroll
        for (int ni = 0; ni < 8; ni++) {
            const int c0 = n0 + wn + ni * 8 + 2 * tq;
            const float bv0 = bias[c0];
            const float bv1 = bias[c0 + 1];
            float v00 = acc[mi][ni][0] + bv0;
            float v01 = acc[mi][ni][1] + bv1;
            float v10 = acc[mi][ni][2] + bv0;
            float v11 = acc[mi][ni][3] + bv1;
            if (EPI == 5) {
                v00 = gelu_t(v00); v01 = gelu_t(v01);
                v10 = gelu_t(v10); v11 = gelu_t(v11);
            }
            if (EPI == 3) {
                __half* Ch = (__half*)C;
                const int hh = c0 >> 6, dd = c0 & 63;
                {
                    const int bb = r0 >> 10, ss = r0 & 1023;
                    *(__half2*)&Ch[(size_t)((bb * H_ + hh) * S_ + ss) * DK_ + dd] =
                        __floats2half2_rn(v00, v01);
                }
                {
                    const int r1 = r0 + 8;
                    const int bb = r1 >> 10, ss = r1 & 1023;
                    *(__half2*)&Ch[(size_t)((bb * H_ + hh) * S_ + ss) * DK_ + dd] =
                        __floats2half2_rn(v10, v11);
                }
            } else if (EPI == 4) {
                __half* Ch = (__half*)C;
                const int hh = c0 >> 6, dd = c0 & 63;
                const int bb = r0 >> 10, ss = r0 & 1023;
                const size_t base = (size_t)((bb * H_ + hh) * DK_ + dd) * S_ + ss;
                Ch[base]           = __float2half_rn(v00);
                Ch[base + S_]      = __float2half_rn(v01);
                Ch[base + 8]       = __float2half_rn(v10);
                Ch[base + S_ + 8]  = __float2half_rn(v11);
            } else {
                __half* Ch = (__half*)C;
                *(__half2*)&Ch[(size_t)r0 * N + c0]       = __floats2half2_rn(v00, v01);
                *(__half2*)&Ch[(size_t)(r0 + 8) * N + c0] = __floats2half2_rn(v10, v11);
            }
        }
    }
}

// ---------------------------------------------------------------------------
// FP16 mma.sync GEMM (R13 config): cp.async 2-stage, ldmatrix + XOR swizzle.
//   CTA 128x128, 128 threads (4 warps 2x2), warp tile 64x64, BK=64.
// ---------------------------------------------------------------------------
#define GSTG 16384                    // bytes per operand stage (128 x 128B)
#define GEMM_SMEM (4 * GSTG)          // 65536 (2 stages x (A,B)) -> 3 CTAs/SM

template <int EPI>
__device__ __forceinline__ void gemm_f16_body(
    const __half* __restrict__ A, const __half* __restrict__ Bt,
    const float* __restrict__ bias, void* __restrict__ C,
    int N, int K, int m0, int n0)
{
    extern __shared__ __half smh[];
    const uint32_t sbase = smem_u32(smh);

    const int tid  = threadIdx.x;
    const int warp = tid >> 5;
    const int lane = tid & 31;
    const int wm = (warp >> 1) * 64;
    const int wn = (warp & 1) * 64;
    const int lq = lane >> 2;
    const int tq = lane & 3;

    // loader: 16 rows x 8 col-granules, swizzled
    const int rr = tid >> 3;             // 0..15
    const int cg = tid & 7;              // col granule 0..7 (16B each)
    const int cs = cg ^ (rr & 7);        // swizzled granule

    const __half* Ap = A  + (size_t)(m0 + rr) * K + cg * 8;
    const __half* Bp = Bt + (size_t)(n0 + rr) * K + cg * 8;
    const uint32_t dA = sbase + (uint32_t)(rr * 128 + cs * 16);
    const uint32_t dB = dA + 2 * GSTG;

    // ldsm lane geometry
    const int msk = lane & 7;
    const int lrA = (lane & 7) + ((lane >> 3) & 1) * 8;
    const int hiA = (lane >> 4) & 1;
    const int lrB = (lane & 7) + ((lane >> 4) & 1) * 8;
    const int hiB = (lane >> 3) & 1;
    const uint32_t baseA = (uint32_t)((wm + lrA) * 128);
    const uint32_t baseB = (uint32_t)((wn + lrB) * 128);

    const int KIT = K >> 6;

    float acc[4][8][4];
#pragma unroll
    for (int mi = 0; mi < 4; mi++)
#pragma unroll
        for (int ni = 0; ni < 8; ni++)
#pragma unroll
            for (int j = 0; j < 4; j++) acc[mi][ni][j] = 0.0f;

    auto issue = [&](int it) {
        if (it < KIT) {
            const __half* a = Ap + it * 64;
            const __half* b = Bp + it * 64;
            const uint32_t off = (uint32_t)(it & 1) * GSTG;
#pragma unroll
            for (int i = 0; i < 8; i++) {     // rows rr + 16i
                cp16(dA + off + (uint32_t)(i * 2048), a + (size_t)(i * 16) * K);
                cp16(dB + off + (uint32_t)(i * 2048), b + (size_t)(i * 16) * K);
            }
        }
        CP_COMMIT;
    };

    issue(0); issue(1);

    for (int it = 0; it < KIT; ++it) {
        CP_WAIT1;
        __syncthreads();
        const uint32_t sA = sbase + (uint32_t)(it & 1) * GSTG;
        const uint32_t sB = sA + 2 * GSTG;

#pragma unroll
        for (int s = 0; s < 4; ++s) {     // 4 x k16
            const uint32_t csA = (uint32_t)(((2 * s + hiA) ^ msk) * 16);
            const uint32_t csB = (uint32_t)(((2 * s + hiB) ^ msk) * 16);
            uint32_t bf[8][2];
#pragma unroll
            for (int p = 0; p < 4; p++) {
                ldsm4(bf[2 * p][0], bf[2 * p][1], bf[2 * p + 1][0], bf[2 * p + 1][1],
                      sB + baseB + (uint32_t)(p * 2048) + csB);
            }
#pragma unroll
            for (int mi = 0; mi < 4; mi++) {
                uint32_t a0, a1, a2, a3;
                ldsm4(a0, a1, a2, a3,
                      sA + baseA + (uint32_t)(mi * 2048) + csA);
#pragma unroll
                for (int ni = 0; ni < 8; ni++)
                    mma16(acc[mi][ni], a0, a1, a2, a3, bf[ni][0], bf[ni][1]);
            }
        }
        __syncthreads();
        issue(it + 2);
    }

    epilogue<EPI>(acc, bias, C, N, m0, n0, wm, wn, lq, tq);
}

template <int EPI>
__global__ void __launch_bounds__(128, 3)
mma_gemm_h(const __half* __restrict__ A, const __half* __restrict__ Bt,
           const float* __restrict__ bias, void* __restrict__ C,
           int N, int K)
{
    gemm_f16_body<EPI>(A, Bt, bias, C, N, K, blockIdx.y * 128, blockIdx.x * 128);
}

// Fully-fused QKV projection: grid.x = 18 (6 tiles x 3 sections).
__global__ void __launch_bounds__(128, 3)
mma_gemm_h_qkv(const __half* __restrict__ A, const __half* __restrict__ wqkvT,
               const float* __restrict__ bq, const float* __restrict__ bk,
               const float* __restrict__ bv,
               __half* __restrict__ oq, __half* __restrict__ ok,
               __half* __restrict__ ovt)
{
    const int z  = blockIdx.x / 6;
    const int n0 = (blockIdx.x % 6) * 128;
    const int m0 = blockIdx.y * 128;
    const __half* Bt = wqkvT + (size_t)z * D_ * D_;
    if (z == 0)      gemm_f16_body<3>(A, Bt, bq, oq,  D_, D_, m0, n0);
    else if (z == 1) gemm_f16_body<3>(A, Bt, bk, ok,  D_, D_, m0, n0);
    else             gemm_f16_body<4>(A, Bt, bv, ovt, D_, D_, m0, n0);
}

// ---------------------------------------------------------------------------
// FP16 tensor-core flash attention, 128-query CTA, 128 threads (4 warps),
// 32 query rows per warp (two 16-row slabs) -> each K/V fragment feeds 2x
// the mma work, halving smem crossbar traffic vs 16-row warps.
// K/V tiles of 128 keys, cp.async double-buffered; two 64-key subtiles.
// Dynamic smem (bytes): K0@0 K1@18432 V0@36864 V1@54272 M0@71680 M1@72192
// ---------------------------------------------------------------------------
#define ATT_K0 0
#define ATT_K1 18432
#define ATT_V0 36864
#define ATT_V1 54272
#define ATT_M0 71680
#define ATT_M1 72192
#define ATT_SMEM 72704

__global__ void __launch_bounds__(128, 2)
flash_attn_f16(const __half* __restrict__ Q,
               const __half* __restrict__ K,
               const __half* __restrict__ Vt,
               const int* __restrict__ mask,
               __half* __restrict__ O)
{
    extern __shared__ char attsm[];
    const uint32_t sb = smem_u32(attsm);

    const int qt = blockIdx.x;    // 0..7 (128-query tiles)
    const int h  = blockIdx.y;
    const int b  = blockIdx.z;
    const int tid  = threadIdx.x;
    const int warp = tid >> 5;    // 0..3, each owns 32 query rows
    const int lane = tid & 31;
    const int lq = lane >> 2;
    const int tq = lane & 3;
    const int bh = b * H_ + h;

    const __half* Kb = K  + (size_t)bh * S_ * DK_;
    const __half* Vb = Vt + (size_t)bh * DK_ * S_;

    auto issueKV = [&](int kt) {
        if (kt < 8) {
            const uint32_t koff = sb + ((kt & 1) ? ATT_K1 : ATT_K0);
            const uint32_t voff = sb + ((kt & 1) ? ATT_V1 : ATT_V0);
            const uint32_t moff = sb + ((kt & 1) ? ATT_M1 : ATT_M0);
            // K: 128 rows x 64 halves, stride 144B; 128 thr -> 1 row each
            {
                const __half* ks = Kb + (size_t)(kt * 128 + tid) * DK_;
                const uint32_t kd = koff + (uint32_t)tid * 144;
#pragma unroll
                for (int i = 0; i < 8; i++) cp16(kd + i * 16, ks + i * 8);
            }
            // V: 64 rows x 128 halves, stride 272B; 128 thr -> half row each
            {
                const int r = tid >> 1, hf = tid & 1;
                const __half* vs = Vb + (size_t)r * S_ + kt * 128 + hf * 64;
                const uint32_t vd = voff + (uint32_t)(r * 272 + hf * 128);
#pragma unroll
                for (int i = 0; i < 8; i++) cp16(vd + i * 16, vs + i * 8);
            }
            cp4(moff + (uint32_t)tid * 4, mask + b * S_ + kt * 128 + tid);
        }
        CP_COMMIT;
    };

    issueKV(0);

    // stage Q (128x64) into K1 region (buffer 1 not yet in flight)
    {
        __half* Qs = (__half*)(attsm + ATT_K1);
        const __half* Qb = Q + (size_t)(bh * S_ + qt * 128) * DK_;
        const uint4* src = (const uint4*)(Qb + (size_t)tid * DK_);
        uint4* dst = (uint4*)&Qs[tid * 72];
#pragma unroll
        for (int i = 0; i < 8; i++) dst[i] = src[i];
    }
    __syncthreads();
    uint32_t qa[2][4][4];
    {
        const uint32_t qbase = sb + ATT_K1;
#pragma unroll
        for (int sl = 0; sl < 2; sl++) {
            const uint32_t loQ = (uint32_t)(((warp * 32 + sl * 16
                                              + ((lane >> 3) & 1) * 8 + (lane & 7)) * 72
                                             + ((lane >> 4) & 1) * 8) * 2);
#pragma unroll
            for (int ks = 0; ks < 4; ks++)
                ldsm4(qa[sl][ks][0], qa[sl][ks][1], qa[sl][ks][2], qa[sl][ks][3],
                      qbase + loQ + (uint32_t)(ks * 16 * 2));
        }
    }
    __syncthreads();

    issueKV(1);

    float o[2][8][4];
#pragma unroll
    for (int sl = 0; sl < 2; sl++)
#pragma unroll
        for (int t = 0; t < 8; t++)
#pragma unroll
            for (int j = 0; j < 4; j++) o[sl][t][j] = 0.0f;
    float l[2][2];
    l[0][0] = l[0][1] = l[1][0] = l[1][1] = 0.0f;

    const uint32_t loK = (uint32_t)(((((lane >> 4) & 1) * 8 + (lane & 7)) * 72
                                     + ((lane >> 3) & 1) * 8) * 2);
    const uint32_t loV = (uint32_t)(((((lane >> 4) & 1) * 8 + (lane & 7)) * 136
                                     + ((lane >> 3) & 1) * 8) * 2);
    const float cE = 0.125f * 1.44269504f;   // exp(s/8) = exp2(s*cE)

    for (int kt = 0; kt < 8; kt++) {
        CP_WAIT1;
        __syncthreads();

        const uint32_t Kbase = sb + ((kt & 1) ? ATT_K1 : ATT_K0);
        const uint32_t Vbase = sb + ((kt & 1) ? ATT_V1 : ATT_V0);
        const int* mk = (const int*)(attsm + ((kt & 1) ? ATT_M1 : ATT_M0));

        // process 128 keys as two 64-key subtiles
#pragma unroll
        for (int hv = 0; hv < 2; hv++) {
            float s[2][8][4];
#pragma unroll
            for (int sl = 0; sl < 2; sl++)
#pragma unroll
                for (int nt = 0; nt < 8; nt++)
#pragma unroll
                    for (int j = 0; j < 4; j++) s[sl][nt][j] = 0.0f;

#pragma unroll
            for (int ks = 0; ks < 4; ks++) {
#pragma unroll
                for (int p = 0; p < 4; p++) {
                    uint32_t b00, b01, b10, b11;
                    ldsm4(b00, b01, b10, b11,
                          Kbase + loK + (uint32_t)(((hv * 4 + p) * 16 * 72 + ks * 16) * 2));
                    mma16(s[0][2 * p],     qa[0][ks][0], qa[0][ks][1], qa[0][ks][2], qa[0][ks][3], b00, b01);
                    mma16(s[0][2 * p + 1], qa[0][ks][0], qa[0][ks][1], qa[0][ks][2], qa[0][ks][3], b10, b11);
                    mma16(s[1][2 * p],     qa[1][ks][0], qa[1][ks][1], qa[1][ks][2], qa[1][ks][3], b00, b01);
                    mma16(s[1][2 * p + 1], qa[1][ks][0], qa[1][ks][1], qa[1][ks][2], qa[1][ks][3], b10, b11);
                }
            }

            // fixed-base softmax: p = exp2(s*cE) (masked -> 0)
#pragma unroll
            for (int sl = 0; sl < 2; sl++) {
                float ps0 = 0.0f, ps1 = 0.0f;
#pragma unroll
                for (int nt = 0; nt < 8; nt++) {
                    const int c = hv * 64 + nt * 8 + 2 * tq;
                    const bool k0 = mk[c] != 0, k1 = mk[c + 1] != 0;
                    const float e0 = k0 ? exp2f(s[sl][nt][0] * cE) : 0.0f;
                    const float e1 = k1 ? exp2f(s[sl][nt][1] * cE) : 0.0f;
                    const float e2 = k0 ? exp2f(s[sl][nt][2] * cE) : 0.0f;
                    const float e3 = k1 ? exp2f(s[sl][nt][3] * cE) : 0.0f;
                    s[sl][nt][0] = e0; s[sl][nt][1] = e1;
                    s[sl][nt][2] = e2; s[sl][nt][3] = e3;
                    ps0 += e0 + e1;
                    ps1 += e2 + e3;
                }
                ps0 += __shfl_xor_sync(0xffffffffu, ps0, 1);
                ps0 += __shfl_xor_sync(0xffffffffu, ps0, 2);
                ps1 += __shfl_xor_sync(0xffffffffu, ps1, 1);
                ps1 += __shfl_xor_sync(0xffffffffu, ps1, 2);
                l[sl][0] += ps0;
                l[sl][1] += ps1;
            }

            // PV over this subtile's 64 keys (V fragments shared by both slabs)
#pragma unroll
            for (int kc = 0; kc < 4; kc++) {
                uint32_t a[2][4];
#pragma unroll
                for (int sl = 0; sl < 2; sl++) {
                    a[sl][0] = pack_f16(s[sl][2 * kc][0],     s[sl][2 * kc][1]);
                    a[sl][1] = pack_f16(s[sl][2 * kc][2],     s[sl][2 * kc][3]);
                    a[sl][2] = pack_f16(s[sl][2 * kc + 1][0], s[sl][2 * kc + 1][1]);
                    a[sl][3] = pack_f16(s[sl][2 * kc + 1][2], s[sl][2 * kc + 1][3]);
                }
#pragma unroll
                for (int tp = 0; tp < 4; tp++) {
                    uint32_t v00, v01, v10, v11;
                    ldsm4(v00, v01, v10, v11,
                          Vbase + loV + (uint32_t)((tp * 16 * 136 + (hv * 4 + kc) * 16) * 2));
                    mma16(o[0][2 * tp],     a[0][0], a[0][1], a[0][2], a[0][3], v00, v01);
                    mma16(o[0][2 * tp + 1], a[0][0], a[0][1], a[0][2], a[0][3], v10, v11);
                    mma16(o[1][2 * tp],     a[1][0], a[1][1], a[1][2], a[1][3], v00, v01);
                    mma16(o[1][2 * tp + 1], a[1][0], a[1][1], a[1][2], a[1][3], v10, v11);
                }
            }
        }
        __syncthreads();
        issueKV(kt + 2);
    }

#pragma unroll
    for (int sl = 0; sl < 2; sl++) {
        const float i0 = 1.0f / l[sl][0];
        const float i1 = 1.0f / l[sl][1];
        const int qr = qt * 128 + warp * 32 + sl * 16 + lq;
        __half* O0 = O + (size_t)(b * S_ + qr) * D_ + h * DK_;
        __half* O1 = O0 + (size_t)8 * D_;
#pragma unroll
        for (int t = 0; t < 8; t++) {
            *(__half2*)(O0 + t * 8 + 2 * tq) =
                __floats2half2_rn(o[sl][t][0] * i0, o[sl][t][1] * i0);
            *(__half2*)(O1 + t * 8 + 2 * tq) =
                __floats2half2_rn(o[sl][t][2] * i1, o[sl][t][3] * i1);
        }
    }
}

// ---------------------------------------------------------------------------
// Fused residual add + LayerNorm (float4/fp16 R, 192 threads);
// optionally writes fp16 copy of the output.
// ---------------------------------------------------------------------------
template <bool WH>
__global__ void __launch_bounds__(192)
ln_residual_kernel(const float* __restrict__ X, const __half* __restrict__ R,
                   const float* __restrict__ ga, const float* __restrict__ gb,
                   float* __restrict__ out, __half* __restrict__ outh)
{
    const int row = blockIdx.x;
    const int t   = threadIdx.x;

    const float4 xv = *(const float4*)(X + (size_t)row * D_ + t * 4);
    const uint2 rv2 = *(const uint2*)(R + (size_t)row * D_ + t * 4);
    const float2 r01 = __half22float2(*(const __half2*)&rv2.x);
    const float2 r23 = __half22float2(*(const __half2*)&rv2.y);
    float4 v;
    v.x = xv.x + r01.x; v.y = xv.y + r01.y;
    v.z = xv.z + r23.x; v.w = xv.w + r23.y;

    __shared__ float sbuf[6];

    float s = (v.x + v.y) + (v.z + v.w);
#pragma unroll
    for (int off = 16; off > 0; off >>= 1) s += __shfl_xor_sync(0xffffffffu, s, off);
    if ((t & 31) == 0) sbuf[t >> 5] = s;
    __syncthreads();
    float tot = 0.f;
#pragma unroll
    for (int i = 0; i < 6; i++) tot += sbuf[i];
    const float mean = tot * (1.0f / (float)D_);
    __syncthreads();

    float4 d;
    d.x = v.x - mean; d.y = v.y - mean;
    d.z = v.z - mean; d.w = v.w - mean;
    float sq = (d.x * d.x + d.y * d.y) + (d.z * d.z + d.w * d.w);
#pragma unroll
    for (int off = 16; off > 0; off >>= 1) sq += __shfl_xor_sync(0xffffffffu, sq, off);
    if ((t & 31) == 0) sbuf[t >> 5] = sq;
    __syncthreads();
    float tot2 = 0.f;
#pragma unroll
    for (int i = 0; i < 6; i++) tot2 += sbuf[i];
    const float var = tot2 * (1.0f / (float)(D_ - 1));
    const float inv = 1.0f / (sqrtf(var) + 1e-6f);

    const float4 gav = *(const float4*)(ga + t * 4);
    const float4 gbv = *(const float4*)(gb + t * 4);
    float4 ov;
    ov.x = gav.x * d.x * inv + gbv.x;
    ov.y = gav.y * d.y * inv + gbv.y;
    ov.z = gav.z * d.z * inv + gbv.z;
    ov.w = gav.w * d.w * inv + gbv.w;
    *(float4*)(out + (size_t)row * D_ + t * 4) = ov;
    if (WH) {
        uint2 hv;
        hv.x = pack_f16(ov.x, ov.y);
        hv.y = pack_f16(ov.z, ov.w);
        *(uint2*)(outh + (size_t)row * D_ + t * 4) = hv;
    }
}

// ---------------------------------------------------------------------------
// Launch
// ---------------------------------------------------------------------------
extern "C" void kernel_launch(void* const* d_in, const int* in_sizes, int n_in,
                              void* d_out, int out_size)
{
    const float* x    = (const float*)d_in[0];
    const int*   mask = (const int*)  d_in[1];
    const float* Wq   = (const float*)d_in[2];
    const float* bq   = (const float*)d_in[3];
    const float* Wk   = (const float*)d_in[4];
    const float* bk   = (const float*)d_in[5];
    const float* Wv   = (const float*)d_in[6];
    const float* bv   = (const float*)d_in[7];
    const float* Wo   = (const float*)d_in[8];
    const float* bo   = (const float*)d_in[9];
    const float* W1   = (const float*)d_in[10];
    const float* b1   = (const float*)d_in[11];
    const float* W2   = (const float*)d_in[12];
    const float* b2   = (const float*)d_in[13];
    const float* ln1a = (const float*)d_in[14];
    const float* ln1b = (const float*)d_in[15];
    const float* ln2a = (const float*)d_in[16];
    const float* ln2b = (const float*)d_in[17];

    __half *xh, *qh, *kh, *vth, *att, *ffh, *o1h, *tmph;
    __half *wqkvT, *woT, *w1T, *w2T;
    float *out1;
    cudaGetSymbolAddress((void**)&xh,    g_xh);
    cudaGetSymbolAddress((void**)&qh,    g_qh);
    cudaGetSymbolAddress((void**)&kh,    g_kh);
    cudaGetSymbolAddress((void**)&vth,   g_vth);
    cudaGetSymbolAddress((void**)&att,   g_att);
    cudaGetSymbolAddress((void**)&ffh,   g_ffh);
    cudaGetSymbolAddress((void**)&o1h,   g_o1h);
    cudaGetSymbolAddress((void**)&tmph,  g_tmph);
    cudaGetSymbolAddress((void**)&out1,  g_out1);
    cudaGetSymbolAddress((void**)&wqkvT, g_wqkvT);
    cudaGetSymbolAddress((void**)&woT,   g_woT);
    cudaGetSymbolAddress((void**)&w1T,   g_w1T);
    cudaGetSymbolAddress((void**)&w2T,   g_w2T);

    cudaFuncSetAttribute(mma_gemm_h<5>,  cudaFuncAttributeMaxDynamicSharedMemorySize, GEMM_SMEM);
    cudaFuncSetAttribute(mma_gemm_h<6>,  cudaFuncAttributeMaxDynamicSharedMemorySize, GEMM_SMEM);
    cudaFuncSetAttribute(mma_gemm_h_qkv, cudaFuncAttributeMaxDynamicSharedMemorySize, GEMM_SMEM);
    cudaFuncSetAttribute(flash_attn_f16, cudaFuncAttributeMaxDynamicSharedMemorySize, ATT_SMEM);

    // Fused prep: all weight transposes + x -> fp16
    prep_kernel<<<13056, 256>>>(x, Wq, Wk, Wv, Wo, W1, W2,
                                (uint2*)xh, wqkvT, woT, w1T, w2T);

    dim3 gProj(D_ / 128, M_ / 128);          // (6, 64)
    dim3 gQkv (3 * D_ / 128, M_ / 128);      // (18, 64)
    dim3 gFfn1(F_ / 128, M_ / 128);          // (24, 64)

    // Fused QKV projection
    mma_gemm_h_qkv<<<gQkv, 128, GEMM_SMEM>>>(xh, wqkvT, bq, bk, bv, qh, kh, vth);

    // Attention (128-query CTAs, 32 q-rows/warp, cp.async pipelined)
    dim3 gAttn(S_ / 128, H_, B_);            // (8, 12, 8)
    flash_attn_f16<<<gAttn, 128, ATT_SMEM>>>(qh, kh, vth, mask, att);

    // Output projection -> fp16 residual branch
    mma_gemm_h<6><<<gProj, 128, GEMM_SMEM>>>(att, woT, bo, tmph, D_, D_);

    // LN1(x + attn_out) -> out1 (fp32) + o1h (fp16)
    ln_residual_kernel<true><<<M_, 192>>>(x, tmph, ln1a, ln1b, out1, o1h);

    // FFN1 (gelu -> fp16) ; FFN2 -> fp16 residual branch
    mma_gemm_h<5><<<gFfn1, 128, GEMM_SMEM>>>(o1h, w1T, b1, ffh, F_, D_);
    mma_gemm_h<6><<<gProj, 128, GEMM_SMEM>>>(ffh, w2T, b2, tmph, D_, F_);

    // LN2(out1 + ffn) -> output
    ln_residual_kernel<false><<<M_, 192>>>(out1, tmph, ln2a, ln2b, (float*)d_out, nullptr);
}

// round 17
// speedup vs baseline: 1.0574x; 1.0574x over previous
#include <cuda_runtime.h>
#include <cuda_fp16.h>
#include <math.h>
#include <stdint.h>

// ---------------------------------------------------------------------------
// Problem constants
// ---------------------------------------------------------------------------
#define B_   8
#define S_   1024
#define D_   768
#define F_   3072
#define H_   12
#define DK_  64
#define M_   (B_ * S_)       // 8192 rows

// ---------------------------------------------------------------------------
// Scratch (device globals; no allocation allowed)
// ---------------------------------------------------------------------------
__device__ __align__(16) __half g_xh [M_ * D_];              // x fp16
__device__ __align__(16) __half g_qh [B_ * H_ * S_ * DK_];   // [B,H,S,dk]
__device__ __align__(16) __half g_kh [B_ * H_ * S_ * DK_];   // [B,H,S,dk]
__device__ __align__(16) __half g_vth[B_ * H_ * DK_ * S_];   // [B,H,dk,S]
__device__ __align__(16) __half g_att[M_ * D_];              // attn out fp16
__device__ __align__(16) __half g_ffh[M_ * F_];              // gelu out fp16
__device__ __align__(16) __half g_o1h[M_ * D_];              // LN1 out fp16
__device__ __align__(16) __half g_tmph[M_ * D_];             // residual branch fp16
// transposed weights, [N, K] K-major, fp16. QKV concatenated.
__device__ __align__(16) __half g_wqkvT[3 * D_ * D_];
__device__ __align__(16) __half g_woT[D_ * D_];
__device__ __align__(16) __half g_w1T[F_ * D_];
__device__ __align__(16) __half g_w2T[D_ * F_];

// ---------------------------------------------------------------------------
// Helpers
// ---------------------------------------------------------------------------
__device__ __forceinline__ uint32_t smem_u32(const void* p) {
    uint32_t a;
    asm("{ .reg .u64 t; cvta.to.shared.u64 t, %1; cvt.u32.u64 %0, t; }"
        : "=r"(a) : "l"(p));
    return a;
}

__device__ __forceinline__ void cp16(uint32_t dst, const void* src) {
    asm volatile("cp.async.cg.shared.global [%0], [%1], 16;"
                 :: "r"(dst), "l"(src) : "memory");
}
__device__ __forceinline__ void cp4(uint32_t dst, const void* src) {
    asm volatile("cp.async.ca.shared.global [%0], [%1], 4;"
                 :: "r"(dst), "l"(src) : "memory");
}
#define CP_COMMIT asm volatile("cp.async.commit_group;" ::: "memory")
#define CP_WAIT1  asm volatile("cp.async.wait_group 1;" ::: "memory")

// m16n8k16 FP16 MMA (fp32 accumulate)
__device__ __forceinline__ void mma16(float* c,
                                      uint32_t a0, uint32_t a1, uint32_t a2, uint32_t a3,
                                      uint32_t b0, uint32_t b1)
{
    asm volatile(
        "mma.sync.aligned.m16n8k16.row.col.f32.f16.f16.f32 "
        "{%0,%1,%2,%3}, {%4,%5,%6,%7}, {%8,%9}, {%0,%1,%2,%3};"
        : "+f"(c[0]), "+f"(c[1]), "+f"(c[2]), "+f"(c[3])
        : "r"(a0), "r"(a1), "r"(a2), "r"(a3), "r"(b0), "r"(b1));
}

// ldmatrix x4 (b16, non-transposed)
__device__ __forceinline__ void ldsm4(uint32_t& r0, uint32_t& r1,
                                      uint32_t& r2, uint32_t& r3, uint32_t addr)
{
    asm volatile("ldmatrix.sync.aligned.m8n8.x4.shared.b16 {%0,%1,%2,%3}, [%4];"
                 : "=r"(r0), "=r"(r1), "=r"(r2), "=r"(r3) : "r"(addr));
}

// pack two fp32 -> f16x2 (lo = first arg)
__device__ __forceinline__ uint32_t pack_f16(float lo, float hi) {
    uint32_t r;
    asm("cvt.rn.f16x2.f32 %0, %1, %2;" : "=r"(r) : "f"(hi), "f"(lo));
    return r;
}

__device__ __forceinline__ float gelu_t(float x) {
    const float c = 0.7978845608028654f;
    float t = tanhf(c * (x + 0.044715f * x * x * x));
    return 0.5f * x * (1.0f + t);
}

// ---------------------------------------------------------------------------
// Fused prep kernel: all 6 weight transposes (fp16) + x -> fp16 conversion.
// ---------------------------------------------------------------------------
__device__ __forceinline__ void transpose_tile_f16(
    const float* __restrict__ W, __half* __restrict__ Wt,
    int K, int N, int k0, int n0, int tx, int ty)
{
    __shared__ float t[32][33];
#pragma unroll
    for (int i = 0; i < 32; i += 8)
        t[ty + i][tx] = W[(size_t)(k0 + ty + i) * N + n0 + tx];
    __syncthreads();
#pragma unroll
    for (int i = 0; i < 32; i += 8)
        Wt[(size_t)(n0 + ty + i) * K + k0 + tx] = __float2half_rn(t[tx][ty + i]);
}

__global__ void __launch_bounds__(256)
prep_kernel(const float* __restrict__ x,
            const float* __restrict__ Wq, const float* __restrict__ Wk,
            const float* __restrict__ Wv, const float* __restrict__ Wo,
            const float* __restrict__ W1, const float* __restrict__ W2,
            uint2* __restrict__ xh, __half* __restrict__ wqkvT,
            __half* __restrict__ woT, __half* __restrict__ w1T,
            __half* __restrict__ w2T)
{
    const int bx  = blockIdx.x;
    const int tid = threadIdx.x;
    const int tx  = tid & 31;
    const int ty  = tid >> 5;

    if (bx < 2304) {
        const int z = bx / 576, t = bx % 576;
        const int kx = t % 24, ny = t / 24;
        const float* W = (z == 0) ? Wq : (z == 1) ? Wk : (z == 2) ? Wv : Wo;
        __half* Wt = (z < 3) ? (wqkvT + (size_t)z * D_ * D_) : woT;
        transpose_tile_f16(W, Wt, D_, D_, kx * 32, ny * 32, tx, ty);
    } else if (bx < 4608) {
        const int t = bx - 2304;
        const int kx = t % 24, ny = t / 24;
        transpose_tile_f16(W1, w1T, D_, F_, kx * 32, ny * 32, tx, ty);
    } else if (bx < 6912) {
        const int t = bx - 4608;
        const int kx = t % 96, ny = t / 96;
        transpose_tile_f16(W2, w2T, F_, D_, kx * 32, ny * 32, tx, ty);
    } else {
        const int i = (bx - 6912) * 256 + tid;
        float4 v = ((const float4*)x)[i];
        uint2 o;
        o.x = pack_f16(v.x, v.y);
        o.y = pack_f16(v.z, v.w);
        xh[i] = o;
    }
}

// ---------------------------------------------------------------------------
// Shared epilogue (fp32 accumulators -> various output formats)
//   EPI: 3 fp16 head-split [B,H,S,dk], 4 fp16 transposed head-split [B,H,dk,S],
//        5 gelu -> fp16 row-major, 6 plain fp16 row-major
// ---------------------------------------------------------------------------
template <int EPI>
__device__ __forceinline__ void epilogue(
    float acc[4][8][4], const float* __restrict__ bias, void* __restrict__ C,
    int N, int m0, int n0, int wm, int wn, int lq, int tq)
{
#pragma unroll
    for (int mi = 0; mi < 4; mi++) {
        const int r0 = m0 + wm + mi * 16 + lq;
#pragma unroll
        for (int ni = 0; ni < 8; ni++) {
            const int c0 = n0 + wn + ni * 8 + 2 * tq;
            const float bv0 = bias[c0];
            const float bv1 = bias[c0 + 1];
            float v00 = acc[mi][ni][0] + bv0;
            float v01 = acc[mi][ni][1] + bv1;
            float v10 = acc[mi][ni][2] + bv0;
            float v11 = acc[mi][ni][3] + bv1;
            if (EPI == 5) {
                v00 = gelu_t(v00); v01 = gelu_t(v01);
                v10 = gelu_t(v10); v11 = gelu_t(v11);
            }
            if (EPI == 3) {
                __half* Ch = (__half*)C;
                const int hh = c0 >> 6, dd = c0 & 63;
                {
                    const int bb = r0 >> 10, ss = r0 & 1023;
                    *(__half2*)&Ch[(size_t)((bb * H_ + hh) * S_ + ss) * DK_ + dd] =
                        __floats2half2_rn(v00, v01);
                }
                {
                    const int r1 = r0 + 8;
                    const int bb = r1 >> 10, ss = r1 & 1023;
                    *(__half2*)&Ch[(size_t)((bb * H_ + hh) * S_ + ss) * DK_ + dd] =
                        __floats2half2_rn(v10, v11);
                }
            } else if (EPI == 4) {
                __half* Ch = (__half*)C;
                const int hh = c0 >> 6, dd = c0 & 63;
                const int bb = r0 >> 10, ss = r0 & 1023;
                const size_t base = (size_t)((bb * H_ + hh) * DK_ + dd) * S_ + ss;
                Ch[base]           = __float2half_rn(v00);
                Ch[base + S_]      = __float2half_rn(v01);
                Ch[base + 8]       = __float2half_rn(v10);
                Ch[base + S_ + 8]  = __float2half_rn(v11);
            } else {
                __half* Ch = (__half*)C;
                *(__half2*)&Ch[(size_t)r0 * N + c0]       = __floats2half2_rn(v00, v01);
                *(__half2*)&Ch[(size_t)(r0 + 8) * N + c0] = __floats2half2_rn(v10, v11);
            }
        }
    }
}

// ---------------------------------------------------------------------------
// FP16 mma.sync GEMM (R13 config): cp.async 2-stage, ldmatrix + XOR swizzle.
//   CTA 128x128, 128 threads (4 warps 2x2), warp tile 64x64, BK=64.
// ---------------------------------------------------------------------------
#define GSTG 16384                    // bytes per operand stage (128 x 128B)
#define GEMM_SMEM (4 * GSTG)          // 65536 (2 stages x (A,B)) -> 3 CTAs/SM

template <int EPI>
__device__ __forceinline__ void gemm_f16_body(
    const __half* __restrict__ A, const __half* __restrict__ Bt,
    const float* __restrict__ bias, void* __restrict__ C,
    int N, int K, int m0, int n0)
{
    extern __shared__ __half smh[];
    const uint32_t sbase = smem_u32(smh);

    const int tid  = threadIdx.x;
    const int warp = tid >> 5;
    const int lane = tid & 31;
    const int wm = (warp >> 1) * 64;
    const int wn = (warp & 1) * 64;
    const int lq = lane >> 2;
    const int tq = lane & 3;

    // loader: 16 rows x 8 col-granules, swizzled
    const int rr = tid >> 3;             // 0..15
    const int cg = tid & 7;              // col granule 0..7 (16B each)
    const int cs = cg ^ (rr & 7);        // swizzled granule

    const __half* Ap = A  + (size_t)(m0 + rr) * K + cg * 8;
    const __half* Bp = Bt + (size_t)(n0 + rr) * K + cg * 8;
    const uint32_t dA = sbase + (uint32_t)(rr * 128 + cs * 16);
    const uint32_t dB = dA + 2 * GSTG;

    // ldsm lane geometry
    const int msk = lane & 7;
    const int lrA = (lane & 7) + ((lane >> 3) & 1) * 8;
    const int hiA = (lane >> 4) & 1;
    const int lrB = (lane & 7) + ((lane >> 4) & 1) * 8;
    const int hiB = (lane >> 3) & 1;
    const uint32_t baseA = (uint32_t)((wm + lrA) * 128);
    const uint32_t baseB = (uint32_t)((wn + lrB) * 128);

    const int KIT = K >> 6;

    float acc[4][8][4];
#pragma unroll
    for (int mi = 0; mi < 4; mi++)
#pragma unroll
        for (int ni = 0; ni < 8; ni++)
#pragma unroll
            for (int j = 0; j < 4; j++) acc[mi][ni][j] = 0.0f;

    auto issue = [&](int it) {
        if (it < KIT) {
            const __half* a = Ap + it * 64;
            const __half* b = Bp + it * 64;
            const uint32_t off = (uint32_t)(it & 1) * GSTG;
#pragma unroll
            for (int i = 0; i < 8; i++) {     // rows rr + 16i
                cp16(dA + off + (uint32_t)(i * 2048), a + (size_t)(i * 16) * K);
                cp16(dB + off + (uint32_t)(i * 2048), b + (size_t)(i * 16) * K);
            }
        }
        CP_COMMIT;
    };

    issue(0); issue(1);

    for (int it = 0; it < KIT; ++it) {
        CP_WAIT1;
        __syncthreads();
        const uint32_t sA = sbase + (uint32_t)(it & 1) * GSTG;
        const uint32_t sB = sA + 2 * GSTG;

#pragma unroll
        for (int s = 0; s < 4; ++s) {     // 4 x k16
            const uint32_t csA = (uint32_t)(((2 * s + hiA) ^ msk) * 16);
            const uint32_t csB = (uint32_t)(((2 * s + hiB) ^ msk) * 16);
            uint32_t bf[8][2];
#pragma unroll
            for (int p = 0; p < 4; p++) {
                ldsm4(bf[2 * p][0], bf[2 * p][1], bf[2 * p + 1][0], bf[2 * p + 1][1],
                      sB + baseB + (uint32_t)(p * 2048) + csB);
            }
#pragma unroll
            for (int mi = 0; mi < 4; mi++) {
                uint32_t a0, a1, a2, a3;
                ldsm4(a0, a1, a2, a3,
                      sA + baseA + (uint32_t)(mi * 2048) + csA);
#pragma unroll
                for (int ni = 0; ni < 8; ni++)
                    mma16(acc[mi][ni], a0, a1, a2, a3, bf[ni][0], bf[ni][1]);
            }
        }
        __syncthreads();
        issue(it + 2);
    }

    epilogue<EPI>(acc, bias, C, N, m0, n0, wm, wn, lq, tq);
}

template <int EPI>
__global__ void __launch_bounds__(128, 3)
mma_gemm_h(const __half* __restrict__ A, const __half* __restrict__ Bt,
           const float* __restrict__ bias, void* __restrict__ C,
           int N, int K)
{
    gemm_f16_body<EPI>(A, Bt, bias, C, N, K, blockIdx.y * 128, blockIdx.x * 128);
}

// Fully-fused QKV projection: grid.x = 18 (6 tiles x 3 sections).
__global__ void __launch_bounds__(128, 3)
mma_gemm_h_qkv(const __half* __restrict__ A, const __half* __restrict__ wqkvT,
               const float* __restrict__ bq, const float* __restrict__ bk,
               const float* __restrict__ bv,
               __half* __restrict__ oq, __half* __restrict__ ok,
               __half* __restrict__ ovt)
{
    const int z  = blockIdx.x / 6;
    const int n0 = (blockIdx.x % 6) * 128;
    const int m0 = blockIdx.y * 128;
    const __half* Bt = wqkvT + (size_t)z * D_ * D_;
    if (z == 0)      gemm_f16_body<3>(A, Bt, bq, oq,  D_, D_, m0, n0);
    else if (z == 1) gemm_f16_body<3>(A, Bt, bk, ok,  D_, D_, m0, n0);
    else             gemm_f16_body<4>(A, Bt, bv, ovt, D_, D_, m0, n0);
}

// ---------------------------------------------------------------------------
// FP16 tensor-core flash attention (R15 config): 128-query CTA, 256 threads
// (8 warps x 16 q-rows), K/V tiles of 128 keys, cp.async double-buffered,
// two 64-key subtiles, fixed-base softmax.
// Dynamic smem (bytes): K0@0 K1@18432 V0@36864 V1@54272 M0@71680 M1@72192
// ---------------------------------------------------------------------------
#define ATT_K0 0
#define ATT_K1 18432
#define ATT_V0 36864
#define ATT_V1 54272
#define ATT_M0 71680
#define ATT_M1 72192
#define ATT_SMEM 72704

__global__ void __launch_bounds__(256, 2)
flash_attn_f16(const __half* __restrict__ Q,
               const __half* __restrict__ K,
               const __half* __restrict__ Vt,
               const int* __restrict__ mask,
               __half* __restrict__ O)
{
    extern __shared__ char attsm[];
    const uint32_t sb = smem_u32(attsm);

    const int qt = blockIdx.x;    // 0..7 (128-query tiles)
    const int h  = blockIdx.y;
    const int b  = blockIdx.z;
    const int tid  = threadIdx.x;
    const int warp = tid >> 5;    // 0..7
    const int lane = tid & 31;
    const int lq = lane >> 2;
    const int tq = lane & 3;
    const int bh = b * H_ + h;

    const __half* Kb = K  + (size_t)bh * S_ * DK_;
    const __half* Vb = Vt + (size_t)bh * DK_ * S_;

    auto issueKV = [&](int kt) {
        if (kt < 8) {
            const uint32_t koff = sb + ((kt & 1) ? ATT_K1 : ATT_K0);
            const uint32_t voff = sb + ((kt & 1) ? ATT_V1 : ATT_V0);
            const uint32_t moff = sb + ((kt & 1) ? ATT_M1 : ATT_M0);
            // K: 128 rows x 64 halves, stride 144B. 256 thr: half-row each.
            {
                const int r = tid >> 1, hf = tid & 1;
                const __half* ks = Kb + (size_t)(kt * 128 + r) * DK_ + hf * 32;
                const uint32_t kd = koff + (uint32_t)(r * 144 + hf * 64);
#pragma unroll
                for (int i = 0; i < 4; i++) cp16(kd + i * 16, ks + i * 8);
            }
            // V: 64 rows x 128 halves, stride 272B. 256 thr: quarter-row each.
            {
                const int r = tid >> 2, q = tid & 3;
                const __half* vs = Vb + (size_t)r * S_ + kt * 128 + q * 32;
                const uint32_t vd = voff + (uint32_t)(r * 272 + q * 64);
#pragma unroll
                for (int i = 0; i < 4; i++) cp16(vd + i * 16, vs + i * 8);
            }
            if (tid < 128)
                cp4(moff + (uint32_t)tid * 4, mask + b * S_ + kt * 128 + tid);
        }
        CP_COMMIT;
    };

    issueKV(0);

    // stage Q (128x64) into K1 region (buffer 1 not yet in flight)
    {
        __half* Qs = (__half*)(attsm + ATT_K1);
        const __half* Qb = Q + (size_t)(bh * S_ + qt * 128) * DK_;
        const int r = tid >> 1, hf = tid & 1;
        const uint4* src = (const uint4*)(Qb + r * DK_ + hf * 32);
        uint4* dst = (uint4*)&Qs[r * 72 + hf * 32];
#pragma unroll
        for (int i = 0; i < 4; i++) dst[i] = src[i];
    }
    __syncthreads();
    uint32_t qa[4][4];
    {
        const uint32_t qbase = sb + ATT_K1;
        const uint32_t loQ = (uint32_t)(((warp * 16 + ((lane >> 3) & 1) * 8 + (lane & 7)) * 72
                                         + ((lane >> 4) & 1) * 8) * 2);
#pragma unroll
        for (int ks = 0; ks < 4; ks++)
            ldsm4(qa[ks][0], qa[ks][1], qa[ks][2], qa[ks][3],
                  qbase + loQ + (uint32_t)(ks * 16 * 2));
    }
    __syncthreads();

    issueKV(1);

    float o[8][4];
#pragma unroll
    for (int t = 0; t < 8; t++)
#pragma unroll
        for (int j = 0; j < 4; j++) o[t][j] = 0.0f;
    float l0 = 0.0f, l1 = 0.0f;

    const uint32_t loK = (uint32_t)(((((lane >> 4) & 1) * 8 + (lane & 7)) * 72
                                     + ((lane >> 3) & 1) * 8) * 2);
    const uint32_t loV = (uint32_t)(((((lane >> 4) & 1) * 8 + (lane & 7)) * 136
                                     + ((lane >> 3) & 1) * 8) * 2);
    const float cE = 0.125f * 1.44269504f;   // exp(s/8) = exp2(s*cE)

    for (int kt = 0; kt < 8; kt++) {
        CP_WAIT1;
        __syncthreads();

        const uint32_t Kbase = sb + ((kt & 1) ? ATT_K1 : ATT_K0);
        const uint32_t Vbase = sb + ((kt & 1) ? ATT_V1 : ATT_V0);
        const int* mk = (const int*)(attsm + ((kt & 1) ? ATT_M1 : ATT_M0));

        // process 128 keys as two 64-key subtiles
#pragma unroll
        for (int hv = 0; hv < 2; hv++) {
            float s[8][4];
#pragma unroll
            for (int nt = 0; nt < 8; nt++)
#pragma unroll
                for (int j = 0; j < 4; j++) s[nt][j] = 0.0f;

#pragma unroll
            for (int ks = 0; ks < 4; ks++) {
#pragma unroll
                for (int p = 0; p < 4; p++) {
                    uint32_t b00, b01, b10, b11;
                    ldsm4(b00, b01, b10, b11,
                          Kbase + loK + (uint32_t)(((hv * 4 + p) * 16 * 72 + ks * 16) * 2));
                    mma16(s[2 * p],     qa[ks][0], qa[ks][1], qa[ks][2], qa[ks][3], b00, b01);
                    mma16(s[2 * p + 1], qa[ks][0], qa[ks][1], qa[ks][2], qa[ks][3], b10, b11);
                }
            }

            // fixed-base softmax: p = exp2(s*cE) (masked -> 0)
            float ps0 = 0.0f, ps1 = 0.0f;
#pragma unroll
            for (int nt = 0; nt < 8; nt++) {
                const int c = hv * 64 + nt * 8 + 2 * tq;
                const bool k0 = mk[c] != 0, k1 = mk[c + 1] != 0;
                const float e0 = k0 ? exp2f(s[nt][0] * cE) : 0.0f;
                const float e1 = k1 ? exp2f(s[nt][1] * cE) : 0.0f;
                const float e2 = k0 ? exp2f(s[nt][2] * cE) : 0.0f;
                const float e3 = k1 ? exp2f(s[nt][3] * cE) : 0.0f;
                s[nt][0] = e0; s[nt][1] = e1; s[nt][2] = e2; s[nt][3] = e3;
                ps0 += e0 + e1;
                ps1 += e2 + e3;
            }
            ps0 += __shfl_xor_sync(0xffffffffu, ps0, 1);
            ps0 += __shfl_xor_sync(0xffffffffu, ps0, 2);
            ps1 += __shfl_xor_sync(0xffffffffu, ps1, 1);
            ps1 += __shfl_xor_sync(0xffffffffu, ps1, 2);
            l0 += ps0;
            l1 += ps1;

            // PV over this subtile's 64 keys
#pragma unroll
            for (int kc = 0; kc < 4; kc++) {
                const uint32_t a0 = pack_f16(s[2 * kc][0],     s[2 * kc][1]);
                const uint32_t a1 = pack_f16(s[2 * kc][2],     s[2 * kc][3]);
                const uint32_t a2 = pack_f16(s[2 * kc + 1][0], s[2 * kc + 1][1]);
                const uint32_t a3 = pack_f16(s[2 * kc + 1][2], s[2 * kc + 1][3]);
#pragma unroll
                for (int tp = 0; tp < 4; tp++) {
                    uint32_t v00, v01, v10, v11;
                    ldsm4(v00, v01, v10, v11,
                          Vbase + loV + (uint32_t)((tp * 16 * 136 + (hv * 4 + kc) * 16) * 2));
                    mma16(o[2 * tp],     a0, a1, a2, a3, v00, v01);
                    mma16(o[2 * tp + 1], a0, a1, a2, a3, v10, v11);
                }
            }
        }
        __syncthreads();
        issueKV(kt + 2);
    }

    const float i0 = 1.0f / l0;
    const float i1 = 1.0f / l1;
    const int qr = qt * 128 + warp * 16 + lq;
    __half* O0 = O + (size_t)(b * S_ + qr) * D_ + h * DK_;
    __half* O1 = O0 + (size_t)8 * D_;
#pragma unroll
    for (int t = 0; t < 8; t++) {
        *(__half2*)(O0 + t * 8 + 2 * tq) = __floats2half2_rn(o[t][0] * i0, o[t][1] * i0);
        *(__half2*)(O1 + t * 8 + 2 * tq) = __floats2half2_rn(o[t][2] * i1, o[t][3] * i1);
    }
}

// ---------------------------------------------------------------------------
// LN1: out = LN(x_fp32 + r_fp16) -> fp16 only (feeds FFN1 and LN2)
// ---------------------------------------------------------------------------
__global__ void __launch_bounds__(192)
ln1_kernel(const float* __restrict__ X, const __half* __restrict__ R,
           const float* __restrict__ ga, const float* __restrict__ gb,
           __half* __restrict__ outh)
{
    const int row = blockIdx.x;
    const int t   = threadIdx.x;

    const float4 xv = *(const float4*)(X + (size_t)row * D_ + t * 4);
    const uint2 rv2 = *(const uint2*)(R + (size_t)row * D_ + t * 4);
    const float2 r01 = __half22float2(*(const __half2*)&rv2.x);
    const float2 r23 = __half22float2(*(const __half2*)&rv2.y);
    float4 v;
    v.x = xv.x + r01.x; v.y = xv.y + r01.y;
    v.z = xv.z + r23.x; v.w = xv.w + r23.y;

    __shared__ float sbuf[6];

    float s = (v.x + v.y) + (v.z + v.w);
#pragma unroll
    for (int off = 16; off > 0; off >>= 1) s += __shfl_xor_sync(0xffffffffu, s, off);
    if ((t & 31) == 0) sbuf[t >> 5] = s;
    __syncthreads();
    float tot = 0.f;
#pragma unroll
    for (int i = 0; i < 6; i++) tot += sbuf[i];
    const float mean = tot * (1.0f / (float)D_);
    __syncthreads();

    float4 d;
    d.x = v.x - mean; d.y = v.y - mean;
    d.z = v.z - mean; d.w = v.w - mean;
    float sq = (d.x * d.x + d.y * d.y) + (d.z * d.z + d.w * d.w);
#pragma unroll
    for (int off = 16; off > 0; off >>= 1) sq += __shfl_xor_sync(0xffffffffu, sq, off);
    if ((t & 31) == 0) sbuf[t >> 5] = sq;
    __syncthreads();
    float tot2 = 0.f;
#pragma unroll
    for (int i = 0; i < 6; i++) tot2 += sbuf[i];
    const float var = tot2 * (1.0f / (float)(D_ - 1));
    const float inv = 1.0f / (sqrtf(var) + 1e-6f);

    const float4 gav = *(const float4*)(ga + t * 4);
    const float4 gbv = *(const float4*)(gb + t * 4);
    uint2 hv;
    hv.x = pack_f16(gav.x * d.x * inv + gbv.x, gav.y * d.y * inv + gbv.y);
    hv.y = pack_f16(gav.z * d.z * inv + gbv.z, gav.w * d.w * inv + gbv.w);
    *(uint2*)(outh + (size_t)row * D_ + t * 4) = hv;
}

// ---------------------------------------------------------------------------
// LN2: out = LN(o1_fp16 + r_fp16) -> fp32 final output
// ---------------------------------------------------------------------------
__global__ void __launch_bounds__(192)
ln2_kernel(const __half* __restrict__ X, const __half* __restrict__ R,
           const float* __restrict__ ga, const float* __restrict__ gb,
           float* __restrict__ out)
{
    const int row = blockIdx.x;
    const int t   = threadIdx.x;

    const uint2 xv2 = *(const uint2*)(X + (size_t)row * D_ + t * 4);
    const uint2 rv2 = *(const uint2*)(R + (size_t)row * D_ + t * 4);
    const float2 x01 = __half22float2(*(const __half2*)&xv2.x);
    const float2 x23 = __half22float2(*(const __half2*)&xv2.y);
    const float2 r01 = __half22float2(*(const __half2*)&rv2.x);
    const float2 r23 = __half22float2(*(const __half2*)&rv2.y);
    float4 v;
    v.x = x01.x + r01.x; v.y = x01.y + r01.y;
    v.z = x23.x + r23.x; v.w = x23.y + r23.y;

    __shared__ float sbuf[6];

    float s = (v.x + v.y) + (v.z + v.w);
#pragma unroll
    for (int off = 16; off > 0; off >>= 1) s += __shfl_xor_sync(0xffffffffu, s, off);
    if ((t & 31) == 0) sbuf[t >> 5] = s;
    __syncthreads();
    float tot = 0.f;
#pragma unroll
    for (int i = 0; i < 6; i++) tot += sbuf[i];
    const float mean = tot * (1.0f / (float)D_);
    __syncthreads();

    float4 d;
    d.x = v.x - mean; d.y = v.y - mean;
    d.z = v.z - mean; d.w = v.w - mean;
    float sq = (d.x * d.x + d.y * d.y) + (d.z * d.z + d.w * d.w);
#pragma unroll
    for (int off = 16; off > 0; off >>= 1) sq += __shfl_xor_sync(0xffffffffu, sq, off);
    if ((t & 31) == 0) sbuf[t >> 5] = sq;
    __syncthreads();
    float tot2 = 0.f;
#pragma unroll
    for (int i = 0; i < 6; i++) tot2 += sbuf[i];
    const float var = tot2 * (1.0f / (float)(D_ - 1));
    const float inv = 1.0f / (sqrtf(var) + 1e-6f);

    const float4 gav = *(const float4*)(ga + t * 4);
    const float4 gbv = *(const float4*)(gb + t * 4);
    float4 ov;
    ov.x = gav.x * d.x * inv + gbv.x;
    ov.y = gav.y * d.y * inv + gbv.y;
    ov.z = gav.z * d.z * inv + gbv.z;
    ov.w = gav.w * d.w * inv + gbv.w;
    *(float4*)(out + (size_t)row * D_ + t * 4) = ov;
}

// ---------------------------------------------------------------------------
// Launch
// ---------------------------------------------------------------------------
extern "C" void kernel_launch(void* const* d_in, const int* in_sizes, int n_in,
                              void* d_out, int out_size)
{
    const float* x    = (const float*)d_in[0];
    const int*   mask = (const int*)  d_in[1];
    const float* Wq   = (const float*)d_in[2];
    const float* bq   = (const float*)d_in[3];
    const float* Wk   = (const float*)d_in[4];
    const float* bk   = (const float*)d_in[5];
    const float* Wv   = (const float*)d_in[6];
    const float* bv   = (const float*)d_in[7];
    const float* Wo   = (const float*)d_in[8];
    const float* bo   = (const float*)d_in[9];
    const float* W1   = (const float*)d_in[10];
    const float* b1   = (const float*)d_in[11];
    const float* W2   = (const float*)d_in[12];
    const float* b2   = (const float*)d_in[13];
    const float* ln1a = (const float*)d_in[14];
    const float* ln1b = (const float*)d_in[15];
    const float* ln2a = (const float*)d_in[16];
    const float* ln2b = (const float*)d_in[17];

    __half *xh, *qh, *kh, *vth, *att, *ffh, *o1h, *tmph;
    __half *wqkvT, *woT, *w1T, *w2T;
    cudaGetSymbolAddress((void**)&xh,    g_xh);
    cudaGetSymbolAddress((void**)&qh,    g_qh);
    cudaGetSymbolAddress((void**)&kh,    g_kh);
    cudaGetSymbolAddress((void**)&vth,   g_vth);
    cudaGetSymbolAddress((void**)&att,   g_att);
    cudaGetSymbolAddress((void**)&ffh,   g_ffh);
    cudaGetSymbolAddress((void**)&o1h,   g_o1h);
    cudaGetSymbolAddress((void**)&tmph,  g_tmph);
    cudaGetSymbolAddress((void**)&wqkvT, g_wqkvT);
    cudaGetSymbolAddress((void**)&woT,   g_woT);
    cudaGetSymbolAddress((void**)&w1T,   g_w1T);
    cudaGetSymbolAddress((void**)&w2T,   g_w2T);

    cudaFuncSetAttribute(mma_gemm_h<5>,  cudaFuncAttributeMaxDynamicSharedMemorySize, GEMM_SMEM);
    cudaFuncSetAttribute(mma_gemm_h<6>,  cudaFuncAttributeMaxDynamicSharedMemorySize, GEMM_SMEM);
    cudaFuncSetAttribute(mma_gemm_h_qkv, cudaFuncAttributeMaxDynamicSharedMemorySize, GEMM_SMEM);
    cudaFuncSetAttribute(flash_attn_f16, cudaFuncAttributeMaxDynamicSharedMemorySize, ATT_SMEM);

    // Fused prep: all weight transposes + x -> fp16
    prep_kernel<<<13056, 256>>>(x, Wq, Wk, Wv, Wo, W1, W2,
                                (uint2*)xh, wqkvT, woT, w1T, w2T);

    dim3 gProj(D_ / 128, M_ / 128);          // (6, 64)
    dim3 gQkv (3 * D_ / 128, M_ / 128);      // (18, 64)
    dim3 gFfn1(F_ / 128, M_ / 128);          // (24, 64)

    // Fused QKV projection
    mma_gemm_h_qkv<<<gQkv, 128, GEMM_SMEM>>>(xh, wqkvT, bq, bk, bv, qh, kh, vth);

    // Attention (128-query CTAs, 256 threads, cp.async pipelined)
    dim3 gAttn(S_ / 128, H_, B_);            // (8, 12, 8)
    flash_attn_f16<<<gAttn, 256, ATT_SMEM>>>(qh, kh, vth, mask, att);

    // Output projection -> fp16 residual branch
    mma_gemm_h<6><<<gProj, 128, GEMM_SMEM>>>(att, woT, bo, tmph, D_, D_);

    // LN1(x + attn_out) -> o1h (fp16 only)
    ln1_kernel<<<M_, 192>>>(x, tmph, ln1a, ln1b, o1h);

    // FFN1 (gelu -> fp16) ; FFN2 -> fp16 residual branch
    mma_gemm_h<5><<<gFfn1, 128, GEMM_SMEM>>>(o1h, w1T, b1, ffh, F_, D_);
    mma_gemm_h<6><<<gProj, 128, GEMM_SMEM>>>(ffh, w2T, b2, tmph, D_, F_);

    // LN2(o1h + ffn) -> fp32 output
    ln2_kernel<<<M_, 192>>>(o1h, tmph, ln2a, ln2b, (float*)d_out);
}